// round 6
// baseline (speedup 1.0000x reference)
#include <cuda_runtime.h>
#include <cstdint>
#include <cstddef>

#define NN   8192
#define DIN  512
#define DH   256
#define DOUT 128
#define CAP  256
#define SLOPE 0.25f
#define FULL 0xffffffffu

// ---- scratch (static device globals; no allocation allowed) ----
__device__ int   g_cols[(size_t)NN * CAP];
__device__ float g_vals[(size_t)NN * CAP];
__device__ int   g_nnz[NN];
__device__ float g_bufA[(size_t)NN * DH];
__device__ float g_bufB[(size_t)NN * DH];
__device__ float g_h[(size_t)NN * DOUT];
__device__ float g_s1[NN];
__device__ float g_s2[NN];
__device__ float g_hmean[DOUT];

__device__ __forceinline__ float leaky(float x) { return x >= 0.f ? x : SLOPE * x; }

// ---------------------------------------------------------------------------
// GEMM body: 64x64 tile, BK=8, 4x8 microtile, 128 threads, double-buffered.
// 2x the resident warps of the 8x8 variant (work = BM*BN/32 threads).
// ---------------------------------------------------------------------------
__device__ __forceinline__ void gemm64x64(
    const float* __restrict__ A, const float* __restrict__ B,
    float* __restrict__ C, int K, int N, int bx, int by, int tid)
{
    __shared__ __align__(16) float As[2][8][68];
    __shared__ __align__(16) float Bs[2][8][68];

    int tx = tid & 7, ty = tid >> 3;          // 8 col-groups x 16 row-groups
    int m0 = by * 64, n0 = bx * 64;

    int arow = tid >> 1, kq = (tid & 1) * 4;  // A: 64x8 tile, 1 float4/thr
    const float* Ap = A + (size_t)(m0 + arow) * K + kq;
    int bk = tid >> 4, bc = (tid & 15) * 4;   // B: 8x64 tile, 1 float4/thr
    const float* Bp = B + (size_t)bk * N + n0 + bc;

    float4 av = *reinterpret_cast<const float4*>(Ap);
    float4 bv = *reinterpret_cast<const float4*>(Bp);
    As[0][kq + 0][arow] = av.x; As[0][kq + 1][arow] = av.y;
    As[0][kq + 2][arow] = av.z; As[0][kq + 3][arow] = av.w;
    *reinterpret_cast<float4*>(&Bs[0][bk][bc]) = bv;
    __syncthreads();

    float acc[4][8];
#pragma unroll
    for (int i = 0; i < 4; i++)
#pragma unroll
        for (int j = 0; j < 8; j++) acc[i][j] = 0.f;

    int ktiles = K >> 3;
    for (int tk = 0; tk < ktiles; tk++) {
        int buf = tk & 1;
        if (tk + 1 < ktiles) {
            av = *reinterpret_cast<const float4*>(Ap + (tk + 1) * 8);
            bv = *reinterpret_cast<const float4*>(Bp + (size_t)(tk + 1) * 8 * N);
        }
#pragma unroll
        for (int k = 0; k < 8; k++) {
            float4 a0 = *reinterpret_cast<const float4*>(&As[buf][k][ty * 4]);
            float4 b0 = *reinterpret_cast<const float4*>(&Bs[buf][k][tx * 8]);
            float4 b1 = *reinterpret_cast<const float4*>(&Bs[buf][k][tx * 8 + 4]);
            float ra[4] = { a0.x, a0.y, a0.z, a0.w };
            float rb[8] = { b0.x, b0.y, b0.z, b0.w, b1.x, b1.y, b1.z, b1.w };
#pragma unroll
            for (int i = 0; i < 4; i++)
#pragma unroll
                for (int j = 0; j < 8; j++) acc[i][j] += ra[i] * rb[j];
        }
        if (tk + 1 < ktiles) {
            int nb = buf ^ 1;
            As[nb][kq + 0][arow] = av.x; As[nb][kq + 1][arow] = av.y;
            As[nb][kq + 2][arow] = av.z; As[nb][kq + 3][arow] = av.w;
            *reinterpret_cast<float4*>(&Bs[nb][bk][bc]) = bv;
        }
        __syncthreads();
    }

#pragma unroll
    for (int i = 0; i < 4; i++) {
        size_t off = (size_t)(m0 + ty * 4 + i) * N + n0 + tx * 8;
        float4 o0 = { acc[i][0], acc[i][1], acc[i][2], acc[i][3] };
        float4 o1 = { acc[i][4], acc[i][5], acc[i][6], acc[i][7] };
        *reinterpret_cast<float4*>(&C[off])     = o0;
        *reinterpret_cast<float4*>(&C[off + 4]) = o1;
    }
}

// ---------------------------------------------------------------------------
// CSR-build body: one block (128 thr) per row; thread owns 64 cols (16 float4).
// ---------------------------------------------------------------------------
__device__ __forceinline__ void csr_body(const float* __restrict__ adj,
                                         int row, int t)
{
    int lane = t & 31, warp = t >> 5;
    const float4* arow = reinterpret_cast<const float4*>(adj + (size_t)row * NN) + t * 16;

    float4 v[16];
    int cnt = 0;
#pragma unroll
    for (int i = 0; i < 16; i++) {
        v[i] = arow[i];
        cnt += (v[i].x > 0.f) + (v[i].y > 0.f) + (v[i].z > 0.f) + (v[i].w > 0.f);
    }

    int inc = cnt;
#pragma unroll
    for (int o = 1; o < 32; o <<= 1) {
        int u = __shfl_up_sync(FULL, inc, o);
        if (lane >= o) inc += u;
    }
    __shared__ int wsum[4], wbase[4];
    if (lane == 31) wsum[warp] = inc;
    __syncthreads();
    if (t == 0) {
        int run = 0;
#pragma unroll
        for (int w = 0; w < 4; w++) { wbase[w] = run; run += wsum[w]; }
        g_nnz[row] = run < CAP ? run : CAP;
    }
    __syncthreads();

    int pos = wbase[warp] + inc - cnt;
    int*   cr = g_cols + (size_t)row * CAP;
    float* vr = g_vals + (size_t)row * CAP;
    int base = t * 64;
#pragma unroll
    for (int i = 0; i < 16; i++) {
        float vv[4] = { v[i].x, v[i].y, v[i].z, v[i].w };
#pragma unroll
        for (int j = 0; j < 4; j++) {
            if (vv[j] > 0.f) {
                if (pos < CAP) { cr[pos] = base + i * 4 + j; vr[pos] = vv[j]; }
                pos++;
            }
        }
    }
}

// Fused launch 1: blocks [0,512) = gemm1 tiles (t1 = x@W1), rest = csr rows.
// gemm is fma-bound, csr is HBM-bound -> they overlap on complementary pipes.
#define G1_BLOCKS 512
__global__ __launch_bounds__(128) void csr_gemm1(
    const float* __restrict__ adj, const float* __restrict__ x,
    const float* __restrict__ W1, float* __restrict__ t1)
{
    int b = blockIdx.x;
    if (b < G1_BLOCKS)
        gemm64x64(x, W1, t1, DIN, DH, b & 3, b >> 2, threadIdx.x);
    else
        csr_body(adj, b - G1_BLOCKS, threadIdx.x);
}

// Standalone GEMM (grid.x = N/64, grid.y = M/64)
__global__ __launch_bounds__(128) void gemm_k(
    const float* __restrict__ A, const float* __restrict__ B,
    float* __restrict__ C, int K, int N)
{
    gemm64x64(A, B, C, K, N, blockIdx.x, blockIdx.y, threadIdx.x);
}

// ---------------------------------------------------------------------------
// Barrier-free SpMM + bias + leaky. 64 lanes/row (float4), 2 rows per block.
// ---------------------------------------------------------------------------
__global__ __launch_bounds__(128) void spmm_leaky(
    const float* __restrict__ T, const float* __restrict__ bias,
    float* __restrict__ O)
{
    int row = blockIdx.x * 2 + (threadIdx.x >> 6);
    int l   = threadIdx.x & 63;
    int nnz = g_nnz[row];
    const int*   cp = g_cols + (size_t)row * CAP;
    const float* vp = g_vals + (size_t)row * CAP;

    float4 a0 = {0,0,0,0}, a1 = {0,0,0,0}, a2 = {0,0,0,0}, a3 = {0,0,0,0};
    int k = 0;
    for (; k + 3 < nnz; k += 4) {
        int   c0 = cp[k], c1 = cp[k+1], c2 = cp[k+2], c3 = cp[k+3];
        float w0 = vp[k], w1 = vp[k+1], w2 = vp[k+2], w3 = vp[k+3];
        float4 v0 = reinterpret_cast<const float4*>(T + (size_t)c0 * DH)[l];
        float4 v1 = reinterpret_cast<const float4*>(T + (size_t)c1 * DH)[l];
        float4 v2 = reinterpret_cast<const float4*>(T + (size_t)c2 * DH)[l];
        float4 v3 = reinterpret_cast<const float4*>(T + (size_t)c3 * DH)[l];
        a0.x += w0*v0.x; a0.y += w0*v0.y; a0.z += w0*v0.z; a0.w += w0*v0.w;
        a1.x += w1*v1.x; a1.y += w1*v1.y; a1.z += w1*v1.z; a1.w += w1*v1.w;
        a2.x += w2*v2.x; a2.y += w2*v2.y; a2.z += w2*v2.z; a2.w += w2*v2.w;
        a3.x += w3*v3.x; a3.y += w3*v3.y; a3.z += w3*v3.z; a3.w += w3*v3.w;
    }
    for (; k < nnz; k++) {
        int c0 = cp[k]; float w0 = vp[k];
        float4 v0 = reinterpret_cast<const float4*>(T + (size_t)c0 * DH)[l];
        a0.x += w0*v0.x; a0.y += w0*v0.y; a0.z += w0*v0.z; a0.w += w0*v0.w;
    }
    float4 b = reinterpret_cast<const float4*>(bias)[l];
    float4 o;
    o.x = leaky(a0.x + a1.x + a2.x + a3.x + b.x);
    o.y = leaky(a0.y + a1.y + a2.y + a3.y + b.y);
    o.z = leaky(a0.z + a1.z + a2.z + a3.z + b.z);
    o.w = leaky(a0.w + a1.w + a2.w + a3.w + b.w);
    reinterpret_cast<float4*>(O + (size_t)row * DH)[l] = o;
}

// ---------------------------------------------------------------------------
// Fused scores (warp-per-row, blocks [0,1024)) + column means (blocks >=1024).
// ---------------------------------------------------------------------------
__global__ __launch_bounds__(256) void scores_hmean(const float* __restrict__ a) {
    int b = blockIdx.x, t = threadIdx.x;
    if (b < NN / 8) {
        int row = b * 8 + (t >> 5);
        int l   = t & 31;
        float4 hv = reinterpret_cast<const float4*>(g_h + (size_t)row * DOUT)[l];
        float4 a1 = reinterpret_cast<const float4*>(a)[l];
        float4 a2 = reinterpret_cast<const float4*>(a + DOUT)[l];
        float r1 = hv.x*a1.x + hv.y*a1.y + hv.z*a1.z + hv.w*a1.w;
        float r2 = hv.x*a2.x + hv.y*a2.y + hv.z*a2.z + hv.w*a2.w;
#pragma unroll
        for (int o = 16; o > 0; o >>= 1) {
            r1 += __shfl_xor_sync(FULL, r1, o);
            r2 += __shfl_xor_sync(FULL, r2, o);
        }
        if (l == 0) { g_s1[row] = r1; g_s2[row] = r2; }
    } else {
        int c = b - NN / 8;
        float s = 0.f;
        for (int r = t; r < NN; r += 256) s += g_h[(size_t)r * DOUT + c];
        __shared__ float red[256];
        red[t] = s;
        __syncthreads();
        for (int ss = 128; ss > 0; ss >>= 1) {
            if (t < ss) red[t] += red[t + ss];
            __syncthreads();
        }
        if (t == 0) g_hmean[c] = red[0] / (float)NN;
    }
}

// ---------------------------------------------------------------------------
// Warp-per-row sparse attention (exact match of dense masked softmax).
// ---------------------------------------------------------------------------
__global__ __launch_bounds__(256) void attn_k(float* __restrict__ out) {
    int warp = threadIdx.x >> 5, l = threadIdx.x & 31;
    int row  = blockIdx.x * 8 + warp;
    int nnz  = g_nnz[row];

    __shared__ float sw[8][CAP];
    __shared__ int   sc[8][CAP];
    float* w = sw[warp];
    int*   c = sc[warp];

    float4 o;
    if (nnz == 0) {
        float4 hm = reinterpret_cast<const float4*>(g_hmean)[l];
        o.x = leaky(hm.x); o.y = leaky(hm.y); o.z = leaky(hm.z); o.w = leaky(hm.w);
    } else {
        float s1i = g_s1[row];
        const int* cp = g_cols + (size_t)row * CAP;
        float m = -3.0e38f;
        for (int k = l; k < nnz; k += 32) {
            int cj = cp[k];
            float e = leaky(s1i + g_s2[cj]);
            c[k] = cj; w[k] = e;
            m = fmaxf(m, e);
        }
        __syncwarp();
#pragma unroll
        for (int off = 16; off > 0; off >>= 1)
            m = fmaxf(m, __shfl_xor_sync(FULL, m, off));
        float s = 0.f;
        for (int k = l; k < nnz; k += 32) {
            float e = expf(w[k] - m);
            w[k] = e; s += e;
        }
        __syncwarp();
#pragma unroll
        for (int off = 16; off > 0; off >>= 1)
            s += __shfl_xor_sync(FULL, s, off);
        float inv = 1.f / s;

        float4 a0 = {0,0,0,0}, a1 = {0,0,0,0};
        int k = 0;
        for (; k + 1 < nnz; k += 2) {
            float w0 = w[k], w1 = w[k+1];
            float4 v0 = reinterpret_cast<const float4*>(g_h + (size_t)c[k]   * DOUT)[l];
            float4 v1 = reinterpret_cast<const float4*>(g_h + (size_t)c[k+1] * DOUT)[l];
            a0.x += w0*v0.x; a0.y += w0*v0.y; a0.z += w0*v0.z; a0.w += w0*v0.w;
            a1.x += w1*v1.x; a1.y += w1*v1.y; a1.z += w1*v1.z; a1.w += w1*v1.w;
        }
        if (k < nnz) {
            float w0 = w[k];
            float4 v0 = reinterpret_cast<const float4*>(g_h + (size_t)c[k] * DOUT)[l];
            a0.x += w0*v0.x; a0.y += w0*v0.y; a0.z += w0*v0.z; a0.w += w0*v0.w;
        }
        o.x = leaky((a0.x + a1.x) * inv);
        o.y = leaky((a0.y + a1.y) * inv);
        o.z = leaky((a0.z + a1.z) * inv);
        o.w = leaky((a0.w + a1.w) * inv);
    }
    if (l < 16)
        *reinterpret_cast<float4*>(out + (size_t)row * 64 + l * 4) = o;
    else
        *reinterpret_cast<float4*>(out + (size_t)NN * 64 + (size_t)row * 64 + (l * 4 - 64)) = o;
}

// ---------------------------------------------------------------------------
extern "C" void kernel_launch(void* const* d_in, const int* in_sizes, int n_in,
                              void* d_out, int out_size)
{
    const float* x   = (const float*)d_in[0];
    const float* adj = (const float*)d_in[1];
    const float* W1  = (const float*)d_in[2];
    const float* b1  = (const float*)d_in[3];
    const float* W2  = (const float*)d_in[4];
    const float* b2  = (const float*)d_in[5];
    const float* Wg  = (const float*)d_in[6];
    const float* a   = (const float*)d_in[7];

    float *pA, *pB, *pH;
    cudaGetSymbolAddress((void**)&pA, g_bufA);
    cudaGetSymbolAddress((void**)&pB, g_bufB);
    cudaGetSymbolAddress((void**)&pH, g_h);

    // t1 = x @ W1 fused with CSR build (independent; overlap fma vs HBM)
    csr_gemm1<<<G1_BLOCKS + NN, 128>>>(adj, x, W1, pA);
    // x1 = leaky(adj @ t1 + b1)
    spmm_leaky<<<NN / 2, 128>>>(pA, b1, pB);
    // t2 = x1 @ W2
    gemm_k<<<dim3(DH / 64, NN / 64), 128>>>(pB, W2, pA, DH, DH);
    // x2 = leaky(adj @ t2 + b2)
    spmm_leaky<<<NN / 2, 128>>>(pA, b2, pB);
    // h = x2 @ Wg
    gemm_k<<<dim3(DOUT / 64, NN / 64), 128>>>(pB, Wg, pH, DH, DOUT);

    scores_hmean<<<NN / 8 + DOUT, 256>>>(a);
    attn_k<<<NN / 8, 256>>>((float*)d_out);
}

// round 7
// speedup vs baseline: 1.0875x; 1.0875x over previous
#include <cuda_runtime.h>
#include <cstdint>
#include <cstddef>

#define NN   8192
#define DIN  512
#define DH   256
#define DOUT 128
#define CAP  256
#define SLOPE 0.25f
#define FULL 0xffffffffu

// ---- scratch (static device globals; no allocation allowed) ----
__device__ int   g_cols[(size_t)NN * CAP];
__device__ float g_vals[(size_t)NN * CAP];
__device__ int   g_nnz[NN];
__device__ float g_bufA[(size_t)NN * DH];
__device__ float g_bufB[(size_t)NN * DH];
__device__ float g_h[(size_t)NN * DOUT];
__device__ float g_s1[NN];
__device__ float g_s2[NN];
__device__ float g_hmean[DOUT];

__device__ __forceinline__ float leaky(float x) { return x >= 0.f ? x : SLOPE * x; }

// ---------------------------------------------------------------------------
// GEMM body: BMxBN tile, BK=8, 8x8 microtile (smem/FFMA balanced),
// double-buffered, register prefetch. THREADS = BM*BN/64.
// ---------------------------------------------------------------------------
template<int BM, int BN>
__device__ __forceinline__ void gemm_body(
    const float* __restrict__ A, const float* __restrict__ B,
    float* __restrict__ C, int K, int N, int bx, int by, int tid)
{
    constexpr int THREADS = BM * BN / 64;
    constexpr int NLA = 2 * BM / THREADS;
    constexpr int NLB = 2 * BN / THREADS;
    constexpr int BN4 = BN / 4;

    __shared__ __align__(16) float As[2][8][BM + 4];
    __shared__ __align__(16) float Bs[2][8][BN + 4];

    int tx = tid % (BN / 8), ty = tid / (BN / 8);
    int m0 = by * BM, n0 = bx * BN;

    const float* Ap[NLA]; int arow[NLA], aq[NLA];
#pragma unroll
    for (int i = 0; i < NLA; i++) {
        int e = tid + i * THREADS;
        arow[i] = e >> 1; aq[i] = (e & 1) * 4;
        Ap[i] = A + (size_t)(m0 + arow[i]) * K + aq[i];
    }
    const float* Bp[NLB]; int bk[NLB], bc[NLB];
#pragma unroll
    for (int i = 0; i < NLB; i++) {
        int f = tid + i * THREADS;
        bk[i] = f / BN4; bc[i] = (f % BN4) * 4;
        Bp[i] = B + (size_t)bk[i] * N + n0 + bc[i];
    }

    float4 avs[NLA], bvs[NLB];
#pragma unroll
    for (int i = 0; i < NLA; i++) avs[i] = *reinterpret_cast<const float4*>(Ap[i]);
#pragma unroll
    for (int i = 0; i < NLB; i++) bvs[i] = *reinterpret_cast<const float4*>(Bp[i]);
#pragma unroll
    for (int i = 0; i < NLA; i++) {
        As[0][aq[i] + 0][arow[i]] = avs[i].x; As[0][aq[i] + 1][arow[i]] = avs[i].y;
        As[0][aq[i] + 2][arow[i]] = avs[i].z; As[0][aq[i] + 3][arow[i]] = avs[i].w;
    }
#pragma unroll
    for (int i = 0; i < NLB; i++)
        *reinterpret_cast<float4*>(&Bs[0][bk[i]][bc[i]]) = bvs[i];
    __syncthreads();

    float acc[8][8];
#pragma unroll
    for (int i = 0; i < 8; i++)
#pragma unroll
        for (int j = 0; j < 8; j++) acc[i][j] = 0.f;

    int ktiles = K >> 3;
    for (int tk = 0; tk < ktiles; tk++) {
        int buf = tk & 1;
        if (tk + 1 < ktiles) {
#pragma unroll
            for (int i = 0; i < NLA; i++)
                avs[i] = *reinterpret_cast<const float4*>(Ap[i] + (tk + 1) * 8);
#pragma unroll
            for (int i = 0; i < NLB; i++)
                bvs[i] = *reinterpret_cast<const float4*>(Bp[i] + (size_t)(tk + 1) * 8 * N);
        }
#pragma unroll
        for (int k = 0; k < 8; k++) {
            float4 a0 = *reinterpret_cast<const float4*>(&As[buf][k][ty * 8]);
            float4 a1 = *reinterpret_cast<const float4*>(&As[buf][k][ty * 8 + 4]);
            float4 b0 = *reinterpret_cast<const float4*>(&Bs[buf][k][tx * 8]);
            float4 b1 = *reinterpret_cast<const float4*>(&Bs[buf][k][tx * 8 + 4]);
            float ra[8] = { a0.x, a0.y, a0.z, a0.w, a1.x, a1.y, a1.z, a1.w };
            float rb[8] = { b0.x, b0.y, b0.z, b0.w, b1.x, b1.y, b1.z, b1.w };
#pragma unroll
            for (int i = 0; i < 8; i++)
#pragma unroll
                for (int j = 0; j < 8; j++) acc[i][j] += ra[i] * rb[j];
        }
        if (tk + 1 < ktiles) {
            int nb = buf ^ 1;
#pragma unroll
            for (int i = 0; i < NLA; i++) {
                As[nb][aq[i] + 0][arow[i]] = avs[i].x; As[nb][aq[i] + 1][arow[i]] = avs[i].y;
                As[nb][aq[i] + 2][arow[i]] = avs[i].z; As[nb][aq[i] + 3][arow[i]] = avs[i].w;
            }
#pragma unroll
            for (int i = 0; i < NLB; i++)
                *reinterpret_cast<float4*>(&Bs[nb][bk[i]][bc[i]]) = bvs[i];
        }
        __syncthreads();
    }

#pragma unroll
    for (int i = 0; i < 8; i++) {
        size_t off = (size_t)(m0 + ty * 8 + i) * N + n0 + tx * 8;
        float4 o0 = { acc[i][0], acc[i][1], acc[i][2], acc[i][3] };
        float4 o1 = { acc[i][4], acc[i][5], acc[i][6], acc[i][7] };
        *reinterpret_cast<float4*>(&C[off])     = o0;
        *reinterpret_cast<float4*>(&C[off + 4]) = o1;
    }
}

// ---------------------------------------------------------------------------
// CSR-build body: one block (128 thr) per row; thread owns 64 cols (16 float4).
// ---------------------------------------------------------------------------
__device__ __forceinline__ void csr_body(const float* __restrict__ adj,
                                         int row, int t)
{
    int lane = t & 31, warp = t >> 5;
    const float4* arow = reinterpret_cast<const float4*>(adj + (size_t)row * NN) + t * 16;

    float4 v[16];
    int cnt = 0;
#pragma unroll
    for (int i = 0; i < 16; i++) {
        v[i] = arow[i];
        cnt += (v[i].x > 0.f) + (v[i].y > 0.f) + (v[i].z > 0.f) + (v[i].w > 0.f);
    }

    int inc = cnt;
#pragma unroll
    for (int o = 1; o < 32; o <<= 1) {
        int u = __shfl_up_sync(FULL, inc, o);
        if (lane >= o) inc += u;
    }
    __shared__ int wsum[4], wbase[4];
    if (lane == 31) wsum[warp] = inc;
    __syncthreads();
    if (t == 0) {
        int run = 0;
#pragma unroll
        for (int w = 0; w < 4; w++) { wbase[w] = run; run += wsum[w]; }
        g_nnz[row] = run < CAP ? run : CAP;
    }
    __syncthreads();

    int pos = wbase[warp] + inc - cnt;
    int*   cr = g_cols + (size_t)row * CAP;
    float* vr = g_vals + (size_t)row * CAP;
    int base = t * 64;
#pragma unroll
    for (int i = 0; i < 16; i++) {
        float vv[4] = { v[i].x, v[i].y, v[i].z, v[i].w };
#pragma unroll
        for (int j = 0; j < 4; j++) {
            if (vv[j] > 0.f) {
                if (pos < CAP) { cr[pos] = base + i * 4 + j; vr[pos] = vv[j]; }
                pos++;
            }
        }
    }
}

// Fused launch 1: blocks [0,256) = gemm1 tiles (t1 = x@W1, 128x64, 8x8 micro),
// blocks [256, 256+NN) = csr rows. fma-bound + HBM-bound -> pipe overlap.
#define G1_BLOCKS 256
__global__ __launch_bounds__(128) void csr_gemm1(
    const float* __restrict__ adj, const float* __restrict__ x,
    const float* __restrict__ W1, float* __restrict__ t1)
{
    int b = blockIdx.x;
    if (b < G1_BLOCKS)
        gemm_body<128, 64>(x, W1, t1, DIN, DH, b & 3, b >> 2, threadIdx.x);
    else
        csr_body(adj, b - G1_BLOCKS, threadIdx.x);
}

// Standalone GEMMs
__global__ __launch_bounds__(128) void gemm_128_64(
    const float* __restrict__ A, const float* __restrict__ B,
    float* __restrict__ C, int K, int N)
{
    gemm_body<128, 64>(A, B, C, K, N, blockIdx.x, blockIdx.y, threadIdx.x);
}

// ---------------------------------------------------------------------------
// Barrier-free SpMM + bias + leaky. 64 lanes/row (float4), 2 rows per block.
// (At the fp32 L2 gather roofline: ~25us per call.)
// ---------------------------------------------------------------------------
__global__ __launch_bounds__(128) void spmm_leaky(
    const float* __restrict__ T, const float* __restrict__ bias,
    float* __restrict__ O)
{
    int row = blockIdx.x * 2 + (threadIdx.x >> 6);
    int l   = threadIdx.x & 63;
    int nnz = g_nnz[row];
    const int*   cp = g_cols + (size_t)row * CAP;
    const float* vp = g_vals + (size_t)row * CAP;

    float4 a0 = {0,0,0,0}, a1 = {0,0,0,0}, a2 = {0,0,0,0}, a3 = {0,0,0,0};
    int k = 0;
    for (; k + 3 < nnz; k += 4) {
        int   c0 = cp[k], c1 = cp[k+1], c2 = cp[k+2], c3 = cp[k+3];
        float w0 = vp[k], w1 = vp[k+1], w2 = vp[k+2], w3 = vp[k+3];
        float4 v0 = reinterpret_cast<const float4*>(T + (size_t)c0 * DH)[l];
        float4 v1 = reinterpret_cast<const float4*>(T + (size_t)c1 * DH)[l];
        float4 v2 = reinterpret_cast<const float4*>(T + (size_t)c2 * DH)[l];
        float4 v3 = reinterpret_cast<const float4*>(T + (size_t)c3 * DH)[l];
        a0.x += w0*v0.x; a0.y += w0*v0.y; a0.z += w0*v0.z; a0.w += w0*v0.w;
        a1.x += w1*v1.x; a1.y += w1*v1.y; a1.z += w1*v1.z; a1.w += w1*v1.w;
        a2.x += w2*v2.x; a2.y += w2*v2.y; a2.z += w2*v2.z; a2.w += w2*v2.w;
        a3.x += w3*v3.x; a3.y += w3*v3.y; a3.z += w3*v3.z; a3.w += w3*v3.w;
    }
    for (; k < nnz; k++) {
        int c0 = cp[k]; float w0 = vp[k];
        float4 v0 = reinterpret_cast<const float4*>(T + (size_t)c0 * DH)[l];
        a0.x += w0*v0.x; a0.y += w0*v0.y; a0.z += w0*v0.z; a0.w += w0*v0.w;
    }
    float4 b = reinterpret_cast<const float4*>(bias)[l];
    float4 o;
    o.x = leaky(a0.x + a1.x + a2.x + a3.x + b.x);
    o.y = leaky(a0.y + a1.y + a2.y + a3.y + b.y);
    o.z = leaky(a0.z + a1.z + a2.z + a3.z + b.z);
    o.w = leaky(a0.w + a1.w + a2.w + a3.w + b.w);
    reinterpret_cast<float4*>(O + (size_t)row * DH)[l] = o;
}

// ---------------------------------------------------------------------------
// Fused scores (warp-per-row, blocks [0,1024)) + column means (blocks >=1024).
// ---------------------------------------------------------------------------
__global__ __launch_bounds__(256) void scores_hmean(const float* __restrict__ a) {
    int b = blockIdx.x, t = threadIdx.x;
    if (b < NN / 8) {
        int row = b * 8 + (t >> 5);
        int l   = t & 31;
        float4 hv = reinterpret_cast<const float4*>(g_h + (size_t)row * DOUT)[l];
        float4 a1 = reinterpret_cast<const float4*>(a)[l];
        float4 a2 = reinterpret_cast<const float4*>(a + DOUT)[l];
        float r1 = hv.x*a1.x + hv.y*a1.y + hv.z*a1.z + hv.w*a1.w;
        float r2 = hv.x*a2.x + hv.y*a2.y + hv.z*a2.z + hv.w*a2.w;
#pragma unroll
        for (int o = 16; o > 0; o >>= 1) {
            r1 += __shfl_xor_sync(FULL, r1, o);
            r2 += __shfl_xor_sync(FULL, r2, o);
        }
        if (l == 0) { g_s1[row] = r1; g_s2[row] = r2; }
    } else {
        int c = b - NN / 8;
        float s = 0.f;
        for (int r = t; r < NN; r += 256) s += g_h[(size_t)r * DOUT + c];
        __shared__ float red[256];
        red[t] = s;
        __syncthreads();
        for (int ss = 128; ss > 0; ss >>= 1) {
            if (t < ss) red[t] += red[t + ss];
            __syncthreads();
        }
        if (t == 0) g_hmean[c] = red[0] / (float)NN;
    }
}

// ---------------------------------------------------------------------------
// Warp-per-row sparse attention (exact match of dense masked softmax).
// ---------------------------------------------------------------------------
__global__ __launch_bounds__(256) void attn_k(float* __restrict__ out) {
    int warp = threadIdx.x >> 5, l = threadIdx.x & 31;
    int row  = blockIdx.x * 8 + warp;
    int nnz  = g_nnz[row];

    __shared__ float sw[8][CAP];
    __shared__ int   sc[8][CAP];
    float* w = sw[warp];
    int*   c = sc[warp];

    float4 o;
    if (nnz == 0) {
        float4 hm = reinterpret_cast<const float4*>(g_hmean)[l];
        o.x = leaky(hm.x); o.y = leaky(hm.y); o.z = leaky(hm.z); o.w = leaky(hm.w);
    } else {
        float s1i = g_s1[row];
        const int* cp = g_cols + (size_t)row * CAP;
        float m = -3.0e38f;
        for (int k = l; k < nnz; k += 32) {
            int cj = cp[k];
            float e = leaky(s1i + g_s2[cj]);
            c[k] = cj; w[k] = e;
            m = fmaxf(m, e);
        }
        __syncwarp();
#pragma unroll
        for (int off = 16; off > 0; off >>= 1)
            m = fmaxf(m, __shfl_xor_sync(FULL, m, off));
        float s = 0.f;
        for (int k = l; k < nnz; k += 32) {
            float e = expf(w[k] - m);
            w[k] = e; s += e;
        }
        __syncwarp();
#pragma unroll
        for (int off = 16; off > 0; off >>= 1)
            s += __shfl_xor_sync(FULL, s, off);
        float inv = 1.f / s;

        float4 a0 = {0,0,0,0}, a1 = {0,0,0,0};
        int k = 0;
        for (; k + 1 < nnz; k += 2) {
            float w0 = w[k], w1 = w[k+1];
            float4 v0 = reinterpret_cast<const float4*>(g_h + (size_t)c[k]   * DOUT)[l];
            float4 v1 = reinterpret_cast<const float4*>(g_h + (size_t)c[k+1] * DOUT)[l];
            a0.x += w0*v0.x; a0.y += w0*v0.y; a0.z += w0*v0.z; a0.w += w0*v0.w;
            a1.x += w1*v1.x; a1.y += w1*v1.y; a1.z += w1*v1.z; a1.w += w1*v1.w;
        }
        if (k < nnz) {
            float w0 = w[k];
            float4 v0 = reinterpret_cast<const float4*>(g_h + (size_t)c[k] * DOUT)[l];
            a0.x += w0*v0.x; a0.y += w0*v0.y; a0.z += w0*v0.z; a0.w += w0*v0.w;
        }
        o.x = leaky((a0.x + a1.x) * inv);
        o.y = leaky((a0.y + a1.y) * inv);
        o.z = leaky((a0.z + a1.z) * inv);
        o.w = leaky((a0.w + a1.w) * inv);
    }
    if (l < 16)
        *reinterpret_cast<float4*>(out + (size_t)row * 64 + l * 4) = o;
    else
        *reinterpret_cast<float4*>(out + (size_t)NN * 64 + (size_t)row * 64 + (l * 4 - 64)) = o;
}

// ---------------------------------------------------------------------------
extern "C" void kernel_launch(void* const* d_in, const int* in_sizes, int n_in,
                              void* d_out, int out_size)
{
    const float* x   = (const float*)d_in[0];
    const float* adj = (const float*)d_in[1];
    const float* W1  = (const float*)d_in[2];
    const float* b1  = (const float*)d_in[3];
    const float* W2  = (const float*)d_in[4];
    const float* b2  = (const float*)d_in[5];
    const float* Wg  = (const float*)d_in[6];
    const float* a   = (const float*)d_in[7];

    float *pA, *pB, *pH;
    cudaGetSymbolAddress((void**)&pA, g_bufA);
    cudaGetSymbolAddress((void**)&pB, g_bufB);
    cudaGetSymbolAddress((void**)&pH, g_h);

    // t1 = x @ W1 fused with CSR build (independent; fma vs HBM overlap)
    csr_gemm1<<<G1_BLOCKS + NN, 128>>>(adj, x, W1, pA);
    // x1 = leaky(adj @ t1 + b1)
    spmm_leaky<<<NN / 2, 128>>>(pA, b1, pB);
    // t2 = x1 @ W2
    gemm_128_64<<<dim3(DH / 64, NN / 128), 128>>>(pB, W2, pA, DH, DH);
    // x2 = leaky(adj @ t2 + b2)
    spmm_leaky<<<NN / 2, 128>>>(pA, b2, pB);
    // h = x2 @ Wg
    gemm_128_64<<<dim3(DOUT / 64, NN / 128), 128>>>(pB, Wg, pH, DH, DOUT);

    scores_hmean<<<NN / 8 + DOUT, 256>>>(a);
    attn_k<<<NN / 8, 256>>>((float*)d_out);
}